// round 4
// baseline (speedup 1.0000x reference)
#include <cuda_runtime.h>
#include <cuda_fp16.h>
#include <math.h>

#define N_LABELS     30000
#define HIDDEN       1024
#define BATCH        256
#define N_EDGES      29999
#define PADDED_EDGES 30000                  // padded with one (0,0) edge

#define BCE_BLOCKS   128                    // CTAs owning 2 batch rows each
#define GRID         148
#define NTHREADS     1024
#define NB           4                      // edges per rec batch
#define BATCH_BYTES  (NB * 2 * HIDDEN * 4)  // 32768
#define NSTAGE       3
#define SMEM_BYTES   120000                 // max(2*30000*2, 3*32768)

// Device globals (no allocation allowed).
__device__ int2     g_edge[PADDED_EDGES];
__device__ double   g_part[GRID][3];
__device__ unsigned g_ticket;
__device__ unsigned g_work;

// ---------------------------------------------------------------------------
// cp.async helpers
// ---------------------------------------------------------------------------
__device__ __forceinline__ void cp_async16(unsigned dst, const void* src) {
    asm volatile("cp.async.cg.shared.global [%0], [%1], 16;\n"
                 :: "r"(dst), "l"(src) : "memory");
}
__device__ __forceinline__ void cp_commit() {
    asm volatile("cp.async.commit_group;\n" ::: "memory");
}
template <int N> __device__ __forceinline__ void cp_wait() {
    asm volatile("cp.async.wait_group %0;\n" :: "n"(N) : "memory");
}

// ---------------------------------------------------------------------------
// Init: convert indices (auto-detect int64 vs int32), pad, reset counters.
// ---------------------------------------------------------------------------
__global__ void init_kernel(const void* __restrict__ par_raw,
                            const void* __restrict__ chi_raw) {
    __shared__ int s_is32;
    if (threadIdx.x == 0) s_is32 = 0;
    __syncthreads();
    if (threadIdx.x < 64) {
        long long v = ((const long long*)par_raw)[threadIdx.x];
        if (v < 0 || v >= (long long)N_LABELS) atomicOr(&s_is32, 1);
    }
    __syncthreads();
    const bool is32 = (s_is32 != 0);

    int i = blockIdx.x * blockDim.x + threadIdx.x;
    if (i < PADDED_EDGES) {
        int p = 0, c = 0;
        if (i < N_EDGES) {
            if (is32) {
                p = ((const int*)par_raw)[i];
                c = ((const int*)chi_raw)[i];
            } else {
                p = (int)((const long long*)par_raw)[i];
                c = (int)((const long long*)chi_raw)[i];
            }
        }
        g_edge[i] = make_int2(p, c);   // pad edge (0,0): diff==0, contributes 0
    }
    if (blockIdx.x == 0 && threadIdx.x == 0) {
        g_work = 0u;
        g_ticket = 0u;
    }
}

// ---------------------------------------------------------------------------
// Reductions (caller syncs between reuses of the scratch array).
// ---------------------------------------------------------------------------
__device__ __forceinline__ float block_reduce_f(float v, float* red) {
    const int lane = threadIdx.x & 31;
    const int wid  = threadIdx.x >> 5;
#pragma unroll
    for (int o = 16; o; o >>= 1) v += __shfl_down_sync(0xffffffffu, v, o);
    if (lane == 0) red[wid] = v;
    __syncthreads();
    float r = 0.f;
    if (wid == 0) {
        r = (lane < (NTHREADS / 32)) ? red[lane] : 0.f;
#pragma unroll
        for (int o = 16; o; o >>= 1) r += __shfl_down_sync(0xffffffffu, r, o);
    }
    return r;  // valid on thread 0
}

__device__ __forceinline__ double block_reduce_d(double v, double* red) {
    const int lane = threadIdx.x & 31;
    const int wid  = threadIdx.x >> 5;
#pragma unroll
    for (int o = 16; o; o >>= 1) v += __shfl_down_sync(0xffffffffu, v, o);
    if (lane == 0) red[wid] = v;
    __syncthreads();
    double r = 0.0;
    if (wid == 0) {
        r = (lane < (NTHREADS / 32)) ? red[lane] : 0.0;
#pragma unroll
        for (int o = 16; o; o >>= 1) r += __shfl_down_sync(0xffffffffu, r, o);
    }
    return r;  // valid on thread 0
}

// ---------------------------------------------------------------------------
// Persistent fused kernel, single wave of 148 CTAs.
//   CTAs [0,128): BCE + prob-reg on 2 rows (fp16x2 MUFU, fp16 smem sigmoids),
//                 then join the rec pipeline.
//   CTAs [128,148): straight to rec.
//   Rec: 3-stage cp.async smem pipeline, CTA-granule work stealing (NB edges
//        per ticket). In-flight bytes live in smem, not registers.
// ---------------------------------------------------------------------------
__global__ void __launch_bounds__(NTHREADS, 1)
mega_kernel(const float* __restrict__ logits,
            const float* __restrict__ targets,
            const float* __restrict__ params,
            float* __restrict__ out) {
    extern __shared__ __align__(16) char smem_raw[];
    __shared__ float    s_redf[32];
    __shared__ double   s_redd[32];
    __shared__ unsigned s_tick;
    __shared__ unsigned s_b0[NSTAGE];
    __shared__ unsigned s_nb;

    const int tid = threadIdx.x;
    double p_bce = 0.0, p_pr = 0.0;

    if (blockIdx.x < BCE_BLOCKS) {
        // ---------------- BCE + prob role ----------------
        __half* s0 = (__half*)smem_raw;
        __half* s1 = (__half*)smem_raw + N_LABELS;
        const int b = blockIdx.x * 2;
        const float4* __restrict__ l0 = (const float4*)(logits  + (size_t)b * N_LABELS);
        const float4* __restrict__ t0 = (const float4*)(targets + (size_t)b * N_LABELS);
        const float4* __restrict__ l1 = (const float4*)(logits  + (size_t)(b + 1) * N_LABELS);
        const float4* __restrict__ t1 = (const float4*)(targets + (size_t)(b + 1) * N_LABELS);
        __half2* s0v = (__half2*)s0;
        __half2* s1v = (__half2*)s1;

        const __half2 one2 = __float2half2_rn(1.f);
        const __half  oneh = __float2half(1.f);
        float bce = 0.f;
        for (int i = tid; i < N_LABELS / 4; i += NTHREADS) {
            float4 la = l0[i], ta = t0[i];
            float4 lb = l1[i], tb = t1[i];
            const float xs[8] = {la.x, la.y, la.z, la.w, lb.x, lb.y, lb.z, lb.w};
            const float ts[8] = {ta.x, ta.y, ta.z, ta.w, tb.x, tb.y, tb.z, tb.w};
            __half sg[8];
#pragma unroll
            for (int k = 0; k < 8; k += 2) {
                __half2 x2 = __floats2half2_rn(xs[k], xs[k + 1]);
                __half2 e  = h2exp(__hneg2(__habs2(x2)));    // exp(-|x|)
                __half2 u  = __hadd2(one2, e);               // 1 + e
                __half2 r  = h2rcp(u);                       // sigmoid(|x|)
                __half2 sp = h2log(u);                       // log1p(e)
                bce += fmaxf(xs[k],     0.f) + __low2float(sp)  - xs[k]     * ts[k];
                bce += fmaxf(xs[k + 1], 0.f) + __high2float(sp) - xs[k + 1] * ts[k + 1];
                __half rl = __low2half(r), rh = __high2half(r);
                sg[k]     = (xs[k]     >= 0.f) ? rl : __hsub(oneh, rl);
                sg[k + 1] = (xs[k + 1] >= 0.f) ? rh : __hsub(oneh, rh);
            }
            s0v[2 * i]     = __halves2half2(sg[0], sg[1]);
            s0v[2 * i + 1] = __halves2half2(sg[2], sg[3]);
            s1v[2 * i]     = __halves2half2(sg[4], sg[5]);
            s1v[2 * i + 1] = __halves2half2(sg[6], sg[7]);
        }
        __syncthreads();

        float pr = 0.f;
        for (int e = tid; e < N_EDGES; e += NTHREADS) {
            int2 pc = g_edge[e];
            float d0 = __half2float(s0[pc.y]) - __half2float(s0[pc.x]);
            float d1 = __half2float(s1[pc.y]) - __half2float(s1[pc.x]);
            pr += fmaxf(d0, 0.f) + fmaxf(d1, 0.f);
        }

        float tb2 = block_reduce_f(bce, s_redf);
        __syncthreads();
        float tp = block_reduce_f(pr, s_redf);
        p_bce = (double)tb2;
        p_pr  = (double)tp;
        __syncthreads();   // done with s0/s1 + s_redf before rec reuses smem
    }

    // ---------------- rec role: cp.async 3-stage pipeline ----------------
    const unsigned smem_u32 =
        (unsigned)__cvta_generic_to_shared(smem_raw);

    // Prologue: fetch 3 tickets, issue 3 batches.
    if (tid == 0) {
#pragma unroll
        for (int s = 0; s < NSTAGE; s++) s_b0[s] = atomicAdd(&g_work, NB);
    }
    __syncthreads();
    unsigned base[NSTAGE];
#pragma unroll
    for (int s = 0; s < NSTAGE; s++) base[s] = s_b0[s];

#pragma unroll
    for (int s = 0; s < NSTAGE; s++) {
        if (base[s] < PADDED_EDGES) {
            const unsigned sbuf = smem_u32 + s * BATCH_BYTES;
#pragma unroll
            for (int k = 0; k < 2; k++) {
                int u    = tid + k * NTHREADS;          // 0..2047
                int e    = u >> 9;
                int half_= (u >> 8) & 1;
                int off  = u & 255;
                int2 pc  = g_edge[base[s] + e];
                int row  = half_ ? pc.y : pc.x;
                cp_async16(sbuf + u * 16,
                           params + (size_t)row * HIDDEN + off * 4);
            }
        }
        cp_commit();
    }

    float acc = 0.f;
    int i = 0;
    while (base[i % NSTAGE] < PADDED_EDGES) {
        const int st = i % NSTAGE;
        cp_wait<NSTAGE - 1>();                 // batch i landed
        if (tid == 0) s_nb = atomicAdd(&g_work, NB);
        __syncthreads();                        // data + next ticket visible

        {   // compute: 1 float4 pair per thread (NB*256 == NTHREADS)
            const float4* buf = (const float4*)(smem_raw + st * BATCH_BYTES);
            int e = tid >> 8, off = tid & 255;
            float4 a = buf[e * 512 + off];
            float4 b = buf[e * 512 + 256 + off];
            float d;
            d = a.x - b.x; acc = fmaf(d, d, acc);
            d = a.y - b.y; acc = fmaf(d, d, acc);
            d = a.z - b.z; acc = fmaf(d, d, acc);
            d = a.w - b.w; acc = fmaf(d, d, acc);
        }
        unsigned nb = s_nb;
        __syncthreads();                        // all done reading buf st

        base[st] = nb;
        if (nb < PADDED_EDGES) {
            const unsigned sbuf = smem_u32 + st * BATCH_BYTES;
#pragma unroll
            for (int k = 0; k < 2; k++) {
                int u    = tid + k * NTHREADS;
                int e    = u >> 9;
                int half_= (u >> 8) & 1;
                int off  = u & 255;
                int2 pc  = g_edge[nb + e];
                int row  = half_ ? pc.y : pc.x;
                cp_async16(sbuf + u * 16,
                           params + (size_t)row * HIDDEN + off * 4);
            }
        }
        cp_commit();
        i++;
    }
    cp_wait<0>();                               // drain before smem reuse/exit
    __syncthreads();

    float tr = block_reduce_f(acc, s_redf);
    double p_rec = (double)tr;

    // ---------------- partials + ticket combine ----------------
    if (tid == 0) {
        g_part[blockIdx.x][0] = p_bce;
        g_part[blockIdx.x][1] = p_rec;
        g_part[blockIdx.x][2] = p_pr;
        __threadfence();
        s_tick = atomicAdd(&g_ticket, 1u);
    }
    __syncthreads();

    if (s_tick == GRID - 1) {
        double sb = 0.0, sr = 0.0, sp = 0.0;
        for (int j = tid; j < GRID; j += NTHREADS) {
            sb += g_part[j][0];
            sr += g_part[j][1];
            sp += g_part[j][2];
        }
        double tb2 = block_reduce_d(sb, s_redd);
        __syncthreads();
        double trr = block_reduce_d(sr, s_redd);
        __syncthreads();
        double tpp = block_reduce_d(sp, s_redd);
        if (tid == 0) {
            out[0] = (float)(tb2 / ((double)BATCH * (double)N_LABELS)
                             + 1e-4 * 0.5 * trr + 1e-4 * tpp);
        }
    }
}

// ---------------------------------------------------------------------------
// Launch. Inputs: logits, targets, params, parent_idx, child_idx. Output: f32.
// ---------------------------------------------------------------------------
extern "C" void kernel_launch(void* const* d_in, const int* in_sizes, int n_in,
                              void* d_out, int out_size) {
    const float* logits  = (const float*)d_in[0];
    const float* targets = (const float*)d_in[1];
    const float* params  = (const float*)d_in[2];
    const void*  par     = d_in[3];
    const void*  chi     = d_in[4];
    float* out = (float*)d_out;
    (void)in_sizes; (void)n_in; (void)out_size;

    cudaFuncSetAttribute(mega_kernel,
                         cudaFuncAttributeMaxDynamicSharedMemorySize, SMEM_BYTES);

    init_kernel<<<(PADDED_EDGES + 255) / 256, 256>>>(par, chi);
    mega_kernel<<<GRID, NTHREADS, SMEM_BYTES>>>(logits, targets, params, out);
}

// round 6
// speedup vs baseline: 1.1920x; 1.1920x over previous
#include <cuda_runtime.h>
#include <cuda_fp16.h>
#include <math.h>

#define N_LABELS  30000
#define HIDDEN    1024
#define BATCH     256
#define N_EDGES   29999

#define NTHREADS  512
#define NWARPS    (NTHREADS / 32)          // 16
#define GRID      296                      // 2 CTAs/SM, all co-resident
#define TOT_WARPS (GRID * NWARPS)          // 4736

#define TILE_W    128
#define N_TILES   ((N_LABELS + TILE_W - 1) / TILE_W)   // 235
#define TPAD      264                       // halves per label row (528 B, 16B-aligned)
#define SMEM_BYTES (TILE_W * TPAD * 2)      // 67584

#define G_REC_E     4                                   // edges per rec granule
#define N_REC_GRAN  ((N_EDGES + G_REC_E - 1) / G_REC_E) // 7500

// Device globals (no allocation allowed).
__device__ __half   g_sig[N_LABELS * BATCH];    // label-major sigmoids (15.36 MB)
__device__ double   g_part[GRID][3];            // bce, rec, prob partials
__device__ unsigned g_work_rec = TOT_WARPS;     // rec granule counter (first = warp id)
__device__ unsigned g_bar      = 0;             // device barrier
__device__ unsigned g_ticket   = 0;             // final-combine ticket

__device__ __forceinline__ int load_idx(const void* p, bool is32, int i) {
    return is32 ? ((const int*)p)[i] : (int)((const long long*)p)[i];
}

__device__ __forceinline__ float block_reduce_f(float v, float* red) {
    const int lane = threadIdx.x & 31;
    const int wid  = threadIdx.x >> 5;
#pragma unroll
    for (int o = 16; o; o >>= 1) v += __shfl_down_sync(0xffffffffu, v, o);
    if (lane == 0) red[wid] = v;
    __syncthreads();
    float r = 0.f;
    if (wid == 0) {
        r = (lane < NWARPS) ? red[lane] : 0.f;
#pragma unroll
        for (int o = 16; o; o >>= 1) r += __shfl_down_sync(0xffffffffu, r, o);
    }
    return r;  // valid on thread 0
}

// ---------------------------------------------------------------------------
// One persistent kernel.
//   CTAs [0,235): transpose tile -> g_sig + bce partial, then join rec pool.
//   CTAs [235,296): rec pool immediately.
//   Rec: warp-granule steal (4 edges = 32 KB per granule), 8-load bursts.
//   Device barrier, then prob gather (static, 512B fp16 rows from L2).
//   Last ticket CTA combines partials, writes scalar, resets counters.
// ---------------------------------------------------------------------------
__global__ void __launch_bounds__(NTHREADS, 2)
mega_kernel(const float* __restrict__ logits,
            const float* __restrict__ targets,
            const float* __restrict__ params,
            const void* __restrict__ par_raw,
            const void* __restrict__ chi_raw,
            float* __restrict__ out) {
    extern __shared__ __align__(16) __half s_tile[];   // [TILE_W][TPAD]
    __shared__ float    s_redf[NWARPS];
    __shared__ int      s_is32;
    __shared__ unsigned s_tick;

    const int tid  = threadIdx.x;
    const int lane = tid & 31;
    const int wid  = tid >> 5;

    // --- dtype detection (per CTA, deterministic, cheap) ---
    if (tid == 0) s_is32 = 0;
    __syncthreads();
    if (tid < 64) {
        long long v = ((const long long*)par_raw)[tid];
        if (v < 0 || v >= (long long)N_LABELS) atomicOr(&s_is32, 1);
    }
    __syncthreads();
    const bool is32 = (s_is32 != 0);

    float bce = 0.f, rec = 0.f, pr = 0.f;

    // =================== Phase A: transpose + BCE ===================
    if (blockIdx.x < N_TILES) {
        const int n0 = blockIdx.x * TILE_W;
        const int nv = min(TILE_W, N_LABELS - n0);

#pragma unroll 1
        for (int pass = 0; pass < BATCH / NWARPS; pass++) {
            const int b = pass * NWARPS + wid;
            const float* __restrict__ lrow = logits  + (size_t)b * N_LABELS + n0;
            const float* __restrict__ trow = targets + (size_t)b * N_LABELS + n0;
#pragma unroll
            for (int j = 0; j < 4; j++) {
                const int nl = lane + 32 * j;
                const bool v = nl < nv;
                float x = v ? lrow[nl] : 0.f;
                float t = v ? trow[nl] : 0.f;
                float e = __expf(-fabsf(x));
                float r = __fdividef(1.f, 1.f + e);    // sigmoid(|x|)
                if (v) {
                    bce += fmaxf(x, 0.f) - __logf(r) - x * t;
                    float sg = (x >= 0.f) ? r : (1.f - r);
                    s_tile[nl * TPAD + b] = __float2half_rn(sg);
                }
            }
        }
        __syncthreads();

        // write-out: 4 threads per label, 8 x 16B chunks each
        {
            const int n = tid >> 2;                    // 0..127
            if (n < nv) {
                const char* src = (const char*)s_tile + (size_t)n * (TPAD * 2);
                char* dst = (char*)g_sig + (size_t)(n0 + n) * (BATCH * 2);
#pragma unroll
                for (int k = 0; k < 8; k++) {
                    const int c = (tid & 3) + 4 * k;   // 0..31
                    *(uint4*)(dst + c * 16) = *(const uint4*)(src + c * 16);
                }
            }
        }
        __syncthreads();   // tile done; s_tile free (unused afterwards)
    }

    // =================== Phase B: rec gather (work-steal) ===================
    {
        unsigned g = blockIdx.x * NWARPS + wid;        // free first granule
        while (g < N_REC_GRAN) {
            const int b4 = (int)g * G_REC_E;
            int k = b4 + (lane & 3);
            if (k > N_EDGES - 1) k = N_EDGES - 1;
            const int vp = load_idx(par_raw, is32, k);
            const int vq = load_idx(chi_raw, is32, k);
            unsigned gn = 0;
            if (lane == 0) gn = atomicAdd(&g_work_rec, 1u);   // prefetch ticket

#pragma unroll
            for (int i = 0; i < G_REC_E; i++) {
                if (b4 + i >= N_EDGES) break;
                const int p = __shfl_sync(0xffffffffu, vp, i);
                const int q = __shfl_sync(0xffffffffu, vq, i);
                const float4* __restrict__ A = (const float4*)params + p * 256 + lane;
                const float4* __restrict__ B = (const float4*)params + q * 256 + lane;
#pragma unroll
                for (int h = 0; h < 2; h++) {
                    float4 a0 = A[h * 128 +  0], a1 = A[h * 128 + 32];
                    float4 a2 = A[h * 128 + 64], a3 = A[h * 128 + 96];
                    float4 b0 = B[h * 128 +  0], b1 = B[h * 128 + 32];
                    float4 b2 = B[h * 128 + 64], b3 = B[h * 128 + 96];
                    float d;
                    d = a0.x - b0.x; rec = fmaf(d, d, rec);
                    d = a0.y - b0.y; rec = fmaf(d, d, rec);
                    d = a0.z - b0.z; rec = fmaf(d, d, rec);
                    d = a0.w - b0.w; rec = fmaf(d, d, rec);
                    d = a1.x - b1.x; rec = fmaf(d, d, rec);
                    d = a1.y - b1.y; rec = fmaf(d, d, rec);
                    d = a1.z - b1.z; rec = fmaf(d, d, rec);
                    d = a1.w - b1.w; rec = fmaf(d, d, rec);
                    d = a2.x - b2.x; rec = fmaf(d, d, rec);
                    d = a2.y - b2.y; rec = fmaf(d, d, rec);
                    d = a2.z - b2.z; rec = fmaf(d, d, rec);
                    d = a2.w - b2.w; rec = fmaf(d, d, rec);
                    d = a3.x - b3.x; rec = fmaf(d, d, rec);
                    d = a3.y - b3.y; rec = fmaf(d, d, rec);
                    d = a3.z - b3.z; rec = fmaf(d, d, rec);
                    d = a3.w - b3.w; rec = fmaf(d, d, rec);
                }
            }
            g = __shfl_sync(0xffffffffu, gn, 0);
        }
    }

    // =================== Device barrier ===================
    __syncthreads();
    if (tid == 0) {
        __threadfence();
        atomicAdd(&g_bar, 1u);
        while (*(volatile unsigned*)&g_bar < GRID) __nanosleep(128);
    }
    __syncthreads();
    __threadfence();   // acquire: g_sig fully visible

    // =================== Phase C: prob gather (static) ===================
    {
        const unsigned gw = blockIdx.x * NWARPS + wid;
        // preload this warp's edge indices (edge = gw + k*TOT_WARPS, k<7)
        int ivp = 0, ivq = 0;
        const int ek = (int)gw + lane * TOT_WARPS;
        if (lane < 7 && ek < N_EDGES) {
            ivp = load_idx(par_raw, is32, ek);
            ivq = load_idx(chi_raw, is32, ek);
        }
        const __half2 z2 = __float2half2_rn(0.f);
#pragma unroll
        for (int k = 0; k < 7; k++) {
            const int e = (int)gw + k * TOT_WARPS;
            if (e >= N_EDGES) break;
            const int p = __shfl_sync(0xffffffffu, ivp, k);
            const int q = __shfl_sync(0xffffffffu, ivq, k);
            const uint4 up = ((const uint4*)g_sig)[p * 32 + lane];
            const uint4 uq = ((const uint4*)g_sig)[q * 32 + lane];
            const __half2* hp = (const __half2*)&up;
            const __half2* hq = (const __half2*)&uq;
#pragma unroll
            for (int m = 0; m < 4; m++) {
                __half2 d = __hmax2(__hsub2(hq[m], hp[m]), z2);
                float2 f = __half22float2(d);
                pr += f.x + f.y;
            }
        }
    }

    // =================== Reduce + ticket combine ===================
    float tb = block_reduce_f(bce, s_redf);
    __syncthreads();
    float tr = block_reduce_f(rec, s_redf);
    __syncthreads();
    float tp = block_reduce_f(pr, s_redf);

    if (tid == 0) {
        g_part[blockIdx.x][0] = (double)tb;
        g_part[blockIdx.x][1] = (double)tr;
        g_part[blockIdx.x][2] = (double)tp;
        __threadfence();
        s_tick = atomicAdd(&g_ticket, 1u);
    }
    __syncthreads();

    if (s_tick == GRID - 1) {
        double sb = 0.0, sr = 0.0, sp = 0.0;
        for (int i = tid; i < GRID; i += NTHREADS) {
            sb += g_part[i][0];
            sr += g_part[i][1];
            sp += g_part[i][2];
        }
        // reuse s_redf as double scratch is unsafe; reduce via shuffles + smem floats
        // do a double block reduction with a local shared buffer
        __shared__ double s_redd[NWARPS];
#pragma unroll
        for (int o = 16; o; o >>= 1) {
            sb += __shfl_down_sync(0xffffffffu, sb, o);
            sr += __shfl_down_sync(0xffffffffu, sr, o);
            sp += __shfl_down_sync(0xffffffffu, sp, o);
        }
        if (lane == 0) s_redd[wid] = sb;
        __syncthreads();
        if (wid == 0) {
            double v = (lane < NWARPS) ? s_redd[lane] : 0.0;
#pragma unroll
            for (int o = 16; o; o >>= 1) v += __shfl_down_sync(0xffffffffu, v, o);
            sb = v;
        }
        __syncthreads();
        if (lane == 0) s_redd[wid] = sr;
        __syncthreads();
        if (wid == 0) {
            double v = (lane < NWARPS) ? s_redd[lane] : 0.0;
#pragma unroll
            for (int o = 16; o; o >>= 1) v += __shfl_down_sync(0xffffffffu, v, o);
            sr = v;
        }
        __syncthreads();
        if (lane == 0) s_redd[wid] = sp;
        __syncthreads();
        if (wid == 0) {
            double v = (lane < NWARPS) ? s_redd[lane] : 0.0;
#pragma unroll
            for (int o = 16; o; o >>= 1) v += __shfl_down_sync(0xffffffffu, v, o);
            sp = v;
        }

        if (tid == 0) {
            out[0] = (float)(sb / ((double)BATCH * (double)N_LABELS)
                             + 1e-4 * (0.5 * sr + sp));
            g_work_rec = TOT_WARPS;   // reset for next replay
            g_bar      = 0u;
            g_ticket   = 0u;
        }
    }
}

// ---------------------------------------------------------------------------
// Launch. Inputs: logits, targets, params, parent_idx, child_idx. Output: f32.
// ---------------------------------------------------------------------------
extern "C" void kernel_launch(void* const* d_in, const int* in_sizes, int n_in,
                              void* d_out, int out_size) {
    const float* logits  = (const float*)d_in[0];
    const float* targets = (const float*)d_in[1];
    const float* params  = (const float*)d_in[2];
    const void*  par     = d_in[3];
    const void*  chi     = d_in[4];
    float* out = (float*)d_out;
    (void)in_sizes; (void)n_in; (void)out_size;

    cudaFuncSetAttribute(mega_kernel,
                         cudaFuncAttributeMaxDynamicSharedMemorySize, SMEM_BYTES);

    mega_kernel<<<GRID, NTHREADS, SMEM_BYTES>>>(logits, targets, params,
                                                par, chi, out);
}

// round 11
// speedup vs baseline: 1.5875x; 1.3318x over previous
#include <cuda_runtime.h>
#include <cuda_fp16.h>
#include <math.h>

#define N_LABELS 30000
#define HIDDEN   1024
#define BATCH    256
#define N_EDGES  29999

#define BCE_BLOCKS 128                    // CTAs owning 2 batch rows each
#define GRID       148
#define NTHREADS   1024
#define NWARPS     (NTHREADS / 32)
#define SMEM_BYTES (2 * N_LABELS * (int)sizeof(__half))   // 120000 B

#define G_REC_E    4                                      // edges per granule
#define N_GRAN     ((N_EDGES + G_REC_E - 1) / G_REC_E)    // 7500

// Device globals (no allocation allowed).
__device__ double   g_part[GRID][3];   // bce, rec, prob partials
__device__ unsigned g_ticket = 0;      // final-combine ticket
__device__ unsigned g_work   = 0;      // rec granule counter

__device__ __forceinline__ int load_idx(const void* p, bool is32, int i) {
    return is32 ? ((const int*)p)[i] : (int)((const long long*)p)[i];
}

__device__ __forceinline__ float block_reduce_f(float v, float* red) {
    const int lane = threadIdx.x & 31;
    const int wid  = threadIdx.x >> 5;
#pragma unroll
    for (int o = 16; o; o >>= 1) v += __shfl_down_sync(0xffffffffu, v, o);
    if (lane == 0) red[wid] = v;
    __syncthreads();
    float r = 0.f;
    if (wid == 0) {
        r = (lane < NWARPS) ? red[lane] : 0.f;
#pragma unroll
        for (int o = 16; o; o >>= 1) r += __shfl_down_sync(0xffffffffu, r, o);
    }
    return r;  // valid on thread 0
}

// ---------------------------------------------------------------------------
// Single persistent kernel, one wave of 148 CTAs, NO pre-processing launch.
//   CTAs [0,128): BCE + prob-reg on 2 batch rows (fp16 smem sigmoid cache),
//                 then join the rec steal pool.
//   CTAs [128,148): straight to the rec pool.
//   Rec: warp-granule stealing (4 edges/ticket, prefetched); indices read raw
//        (int64 or int32, auto-detected per CTA).
//   Last CTA combines partials, writes the scalar, resets counters.
// ---------------------------------------------------------------------------
__global__ void __launch_bounds__(NTHREADS, 1)
mega_kernel(const float* __restrict__ logits,
            const float* __restrict__ targets,
            const float* __restrict__ params,
            const void* __restrict__ par_raw,
            const void* __restrict__ chi_raw,
            float* __restrict__ out) {
    extern __shared__ __align__(16) char smem_raw[];
    __shared__ float    s_redf[NWARPS];
    __shared__ int      s_is32;
    __shared__ unsigned s_tick;

    const int tid  = threadIdx.x;
    const int lane = tid & 31;
    const int wid  = tid >> 5;

    // --- dtype detection (per CTA) ---
    if (tid == 0) s_is32 = 0;
    __syncthreads();
    if (tid < 64) {
        long long v = ((const long long*)par_raw)[tid];
        if (v < 0 || v >= (long long)N_LABELS) atomicOr(&s_is32, 1);
    }
    __syncthreads();
    const bool is32 = (s_is32 != 0);

    double p_bce = 0.0, p_pr = 0.0;

    if (blockIdx.x < BCE_BLOCKS) {
        // ---------------- BCE + prob role ----------------
        __half* s0 = (__half*)smem_raw;
        __half* s1 = (__half*)smem_raw + N_LABELS;
        const int b = blockIdx.x * 2;
        const float4* __restrict__ l0 = (const float4*)(logits  + (size_t)b * N_LABELS);
        const float4* __restrict__ t0 = (const float4*)(targets + (size_t)b * N_LABELS);
        const float4* __restrict__ l1 = (const float4*)(logits  + (size_t)(b + 1) * N_LABELS);
        const float4* __restrict__ t1 = (const float4*)(targets + (size_t)(b + 1) * N_LABELS);
        __half2* s0v = (__half2*)s0;
        __half2* s1v = (__half2*)s1;

        float bce = 0.f;
        for (int i = tid; i < N_LABELS / 4; i += NTHREADS) {
            float4 la = l0[i], ta = t0[i];
            float4 lb = l1[i], tb = t1[i];
            const float xs[8] = {la.x, la.y, la.z, la.w, lb.x, lb.y, lb.z, lb.w};
            const float ts[8] = {ta.x, ta.y, ta.z, ta.w, tb.x, tb.y, tb.z, tb.w};
            float sg[8];
#pragma unroll
            for (int k = 0; k < 8; k++) {
                float x = xs[k];
                float e = __expf(-fabsf(x));
                float r = __frcp_rn(1.f + e);           // sigmoid(|x|)
                bce += fmaxf(x, 0.f) - __logf(r) - x * ts[k];
                sg[k] = (x >= 0.f) ? r : (1.f - r);
            }
            s0v[2 * i]     = __floats2half2_rn(sg[0], sg[1]);
            s0v[2 * i + 1] = __floats2half2_rn(sg[2], sg[3]);
            s1v[2 * i]     = __floats2half2_rn(sg[4], sg[5]);
            s1v[2 * i + 1] = __floats2half2_rn(sg[6], sg[7]);
        }
        __syncthreads();

        float pr = 0.f;
        for (int e = tid; e < N_EDGES; e += NTHREADS) {
            int p = load_idx(par_raw, is32, e);
            int c = load_idx(chi_raw, is32, e);
            float d0 = __half2float(s0[c]) - __half2float(s0[p]);
            float d1 = __half2float(s1[c]) - __half2float(s1[p]);
            pr += fmaxf(d0, 0.f) + fmaxf(d1, 0.f);
        }

        float tb2 = block_reduce_f(bce, s_redf);
        __syncthreads();
        float tp = block_reduce_f(pr, s_redf);
        p_bce = (double)tb2;
        p_pr  = (double)tp;
        __syncthreads();   // s_redf reused by the rec reduction below
    }

    // ---------------- rec role: warp-granule work stealing ----------------
    float rec0 = 0.f, rec1 = 0.f;
    {
        unsigned g = 0xffffffffu;
        if (lane == 0) g = atomicAdd(&g_work, 1u);
        g = __shfl_sync(0xffffffffu, g, 0);
        while (g < N_GRAN) {
            const int b4 = (int)g * G_REC_E;
            int k = b4 + (lane & 3);
            if (k > N_EDGES - 1) k = N_EDGES - 1;
            const int vp = load_idx(par_raw, is32, k);
            const int vq = load_idx(chi_raw, is32, k);
            unsigned gn = 0xffffffffu;
            if (lane == 0) gn = atomicAdd(&g_work, 1u);    // prefetch ticket

#pragma unroll
            for (int i = 0; i < G_REC_E; i++) {
                if (b4 + i >= N_EDGES) break;
                const int p = __shfl_sync(0xffffffffu, vp, i);
                const int q = __shfl_sync(0xffffffffu, vq, i);
                const float4* __restrict__ A = (const float4*)params + p * 256 + lane;
                const float4* __restrict__ B = (const float4*)params + q * 256 + lane;
#pragma unroll
                for (int h = 0; h < 2; h++) {
                    float4 a0 = A[h * 128 +  0], a1 = A[h * 128 + 32];
                    float4 a2 = A[h * 128 + 64], a3 = A[h * 128 + 96];
                    float4 b0 = B[h * 128 +  0], b1 = B[h * 128 + 32];
                    float4 b2 = B[h * 128 + 64], b3 = B[h * 128 + 96];
                    float d;
                    d = a0.x - b0.x; rec0 = fmaf(d, d, rec0);
                    d = a0.y - b0.y; rec1 = fmaf(d, d, rec1);
                    d = a0.z - b0.z; rec0 = fmaf(d, d, rec0);
                    d = a0.w - b0.w; rec1 = fmaf(d, d, rec1);
                    d = a1.x - b1.x; rec0 = fmaf(d, d, rec0);
                    d = a1.y - b1.y; rec1 = fmaf(d, d, rec1);
                    d = a1.z - b1.z; rec0 = fmaf(d, d, rec0);
                    d = a1.w - b1.w; rec1 = fmaf(d, d, rec1);
                    d = a2.x - b2.x; rec0 = fmaf(d, d, rec0);
                    d = a2.y - b2.y; rec1 = fmaf(d, d, rec1);
                    d = a2.z - b2.z; rec0 = fmaf(d, d, rec0);
                    d = a2.w - b2.w; rec1 = fmaf(d, d, rec1);
                    d = a3.x - b3.x; rec0 = fmaf(d, d, rec0);
                    d = a3.y - b3.y; rec1 = fmaf(d, d, rec1);
                    d = a3.z - b3.z; rec0 = fmaf(d, d, rec0);
                    d = a3.w - b3.w; rec1 = fmaf(d, d, rec1);
                }
            }
            g = __shfl_sync(0xffffffffu, gn, 0);
        }
    }

    float tr = block_reduce_f(rec0 + rec1, s_redf);
    double p_rec = (double)tr;

    // ---------------- partials + ticket combine ----------------
    if (tid == 0) {
        g_part[blockIdx.x][0] = p_bce;
        g_part[blockIdx.x][1] = p_rec;
        g_part[blockIdx.x][2] = p_pr;
        __threadfence();
        s_tick = atomicAdd(&g_ticket, 1u);
    }
    __syncthreads();

    if (s_tick == GRID - 1) {
        __shared__ double s_redd[NWARPS];
        double sb = 0.0, sr = 0.0, sp = 0.0;
        for (int i = tid; i < GRID; i += NTHREADS) {
            sb += g_part[i][0];
            sr += g_part[i][1];
            sp += g_part[i][2];
        }
#pragma unroll
        for (int o = 16; o; o >>= 1) {
            sb += __shfl_down_sync(0xffffffffu, sb, o);
            sr += __shfl_down_sync(0xffffffffu, sr, o);
            sp += __shfl_down_sync(0xffffffffu, sp, o);
        }
        if (lane == 0) s_redd[wid] = sb;
        __syncthreads();
        if (wid == 0) {
            double v = (lane < NWARPS) ? s_redd[lane] : 0.0;
#pragma unroll
            for (int o = 16; o; o >>= 1) v += __shfl_down_sync(0xffffffffu, v, o);
            sb = v;
        }
        __syncthreads();
        if (lane == 0) s_redd[wid] = sr;
        __syncthreads();
        if (wid == 0) {
            double v = (lane < NWARPS) ? s_redd[lane] : 0.0;
#pragma unroll
            for (int o = 16; o; o >>= 1) v += __shfl_down_sync(0xffffffffu, v, o);
            sr = v;
        }
        __syncthreads();
        if (lane == 0) s_redd[wid] = sp;
        __syncthreads();
        if (wid == 0) {
            double v = (lane < NWARPS) ? s_redd[lane] : 0.0;
#pragma unroll
            for (int o = 16; o; o >>= 1) v += __shfl_down_sync(0xffffffffu, v, o);
            sp = v;
        }
        if (tid == 0) {
            out[0] = (float)(sb / ((double)BATCH * (double)N_LABELS)
                             + 1e-4 * (0.5 * sr + sp));
            g_work   = 0u;    // reset for next graph replay
            g_ticket = 0u;
        }
    }
}

// ---------------------------------------------------------------------------
// Launch. Inputs: logits, targets, params, parent_idx, child_idx. Output: f32.
// ---------------------------------------------------------------------------
extern "C" void kernel_launch(void* const* d_in, const int* in_sizes, int n_in,
                              void* d_out, int out_size) {
    const float* logits  = (const float*)d_in[0];
    const float* targets = (const float*)d_in[1];
    const float* params  = (const float*)d_in[2];
    const void*  par     = d_in[3];
    const void*  chi     = d_in[4];
    float* out = (float*)d_out;
    (void)in_sizes; (void)n_in; (void)out_size;

    cudaFuncSetAttribute(mega_kernel,
                         cudaFuncAttributeMaxDynamicSharedMemorySize, SMEM_BYTES);

    mega_kernel<<<GRID, NTHREADS, SMEM_BYTES>>>(logits, targets, params,
                                                par, chi, out);
}